// round 2
// baseline (speedup 1.0000x reference)
#include <cuda_runtime.h>
#include <cuda_bf16.h>

#define TOKENS 32768
#define DDIM 1024
#define RDIM 48
#define MTILE 128
#define NCTAS (TOKENS / MTILE)   // 256
#define KC 128
#define XS_STRIDE 136            // bf16 elems; 272B row stride -> conflict-free frag loads
#define GW_STRIDE 1032           // bf16 elems; 2064B row stride
#define YS_STRIDE 52
#define WU_STRIDE 56             // 112B row stride
#define H2_STRIDE 56

// ---- scratch / precomputed weights (device globals: no allocation allowed) ----
__device__ __align__(16) __nv_bfloat16 g_gw[RDIM * DDIM];   // gamma ⊙ w_down, bf16
__device__ __align__(16) __nv_bfloat16 g_wu[DDIM * RDIM];   // w_up, bf16
__device__ __align__(16) __nv_bfloat16 g_h2[TOKENS * RDIM]; // intermediate activations
__device__ float g_sumgw[RDIM];
__device__ float g_cb[RDIM];
__device__ float g_c48[RDIM];
__device__ float g_A48T[RDIM * RDIM];                       // A48T[r'][r]

__device__ __forceinline__ float gelu_exact(float v) {
    return 0.5f * v * (1.0f + erff(v * 0.70710678118654752440f));
}

__device__ __forceinline__ void mma_bf16(float* c, unsigned a0, unsigned a1, unsigned a2,
                                         unsigned a3, unsigned b0, unsigned b1) {
    asm volatile(
        "mma.sync.aligned.m16n8k16.row.col.f32.bf16.bf16.f32 "
        "{%0,%1,%2,%3}, {%4,%5,%6,%7}, {%8,%9}, {%0,%1,%2,%3};\n"
        : "+f"(c[0]), "+f"(c[1]), "+f"(c[2]), "+f"(c[3])
        : "r"(a0), "r"(a1), "r"(a2), "r"(a3), "r"(b0), "r"(b1));
}

// ============================================================================
// prep: fold LN-gamma into w_down (bf16), row sums, collapse the W=1 middle
// (to_mv -> EquiLinear -> from_mv) into a single 48x48 matrix A48 + bias c48.
// ============================================================================
__global__ void prep_kernel(const float* __restrict__ gamma, const float* __restrict__ beta,
                            const float* __restrict__ w_down, const float* __restrict__ w_to_mv,
                            const float* __restrict__ w_equi, const float* __restrict__ b_equi,
                            const float* __restrict__ w_from_mv, const float* __restrict__ w_up) {
    int tid = threadIdx.x, lane = tid & 31;
    int gtid = blockIdx.x * blockDim.x + tid;
    int nth = gridDim.x * blockDim.x;
    int gwarp = gtid >> 5;

    if (gwarp < RDIM) {  // one warp per down-proj row
        int r = gwarp;
        float s = 0.f, cb = 0.f;
        for (int d = lane; d < DDIM; d += 32) {
            float w = w_down[r * DDIM + d];
            float gw = w * gamma[d];
            g_gw[r * DDIM + d] = __float2bfloat16(gw);
            s += gw;
            cb += w * beta[d];
        }
        #pragma unroll
        for (int off = 16; off; off >>= 1) {
            s  += __shfl_xor_sync(0xffffffffu, s, off);
            cb += __shfl_xor_sync(0xffffffffu, cb, off);
        }
        if (lane == 0) { g_sumgw[r] = s; g_cb[r] = cb; }
    }
    for (int i = gtid; i < DDIM * RDIM; i += nth)
        g_wu[i] = __float2bfloat16(w_up[i]);
    for (int i = gtid; i < RDIM * RDIM; i += nth) {
        int rp = i / RDIM, r = i % RDIM;
        float a = 0.f;
        #pragma unroll
        for (int m = 0; m < 16; m++) {
            int gidx = (m == 0) ? 0 : (m < 5) ? 1 : (m < 11) ? 2 : (m < 15) ? 3 : 4;
            a += w_from_mv[r * 16 + m] * w_equi[gidx] * w_to_mv[m * RDIM + rp];
        }
        g_A48T[i] = a;  // A48T[rp][r]
    }
    for (int i = gtid; i < RDIM; i += nth)
        g_c48[i] = w_from_mv[i * 16 + 0] * b_equi[0];
}

// ============================================================================
// k1: per 128-token tile — stream x once, accumulate LN stats + x@gwT via mma,
// apply LN affine + gelu, 48x48 middle matvec + gelu, write h2 (bf16).
// ============================================================================
__global__ __launch_bounds__(256) void k1_kernel(const float* __restrict__ x) {
    extern __shared__ char smem[];
    __nv_bfloat16* gw_s = (__nv_bfloat16*)smem;                                     // 99072 B
    __nv_bfloat16* x_s  = (__nv_bfloat16*)(smem + RDIM * GW_STRIDE * 2);            // 34816 B
    float* y_s    = (float*)(smem + RDIM * GW_STRIDE * 2 + MTILE * XS_STRIDE * 2);  // 26624 B
    float* sum_s  = y_s + MTILE * YS_STRIDE;
    float* sumsq_s = sum_s + MTILE;
    float* sumgw_s = sumsq_s + MTILE;
    float* cb_s   = sumgw_s + RDIM;
    float* c48_s  = cb_s + RDIM;
    float* A48T_s = c48_s + RDIM;

    int tid = threadIdx.x, lane = tid & 31, warp = tid >> 5;
    int g = lane >> 2, t4 = lane & 3;
    int tok0 = blockIdx.x * MTILE;

    // stage weights
    for (int i = tid; i < RDIM * (DDIM / 8); i += 256) {
        int r = i >> 7, c8 = i & 127;
        *((uint4*)(gw_s + r * GW_STRIDE + c8 * 8)) = ((const uint4*)g_gw)[i];
    }
    for (int i = tid; i < RDIM; i += 256) {
        sumgw_s[i] = g_sumgw[i]; cb_s[i] = g_cb[i]; c48_s[i] = g_c48[i];
    }
    for (int i = tid; i < RDIM * RDIM; i += 256) A48T_s[i] = g_A48T[i];
    if (tid < MTILE) { sum_s[tid] = 0.f; sumsq_s[tid] = 0.f; }
    __syncthreads();

    float acc[6][4];
    #pragma unroll
    for (int j = 0; j < 6; j++)
        #pragma unroll
        for (int q = 0; q < 4; q++) acc[j][q] = 0.f;

    int mrow = warp * 16;
    for (int kc = 0; kc < DDIM / KC; kc++) {
        const float* xb = x + (size_t)tok0 * DDIM + kc * KC;
        // each warp loads rows {w, w+8, ..., w+120}: full 512B coalesced rows
        #pragma unroll
        for (int i = 0; i < 16; i++) {
            int row = i * 8 + warp;
            float4 v = *(const float4*)(xb + (size_t)row * DDIM + lane * 4);
            float ps  = v.x + v.y + v.z + v.w;
            float pss = v.x * v.x + v.y * v.y + v.z * v.z + v.w * v.w;
            #pragma unroll
            for (int off = 16; off; off >>= 1) {
                ps  += __shfl_xor_sync(0xffffffffu, ps, off);
                pss += __shfl_xor_sync(0xffffffffu, pss, off);
            }
            if (lane == 0) { sum_s[row] += ps; sumsq_s[row] += pss; }  // row unique to warp
            __nv_bfloat162 p0 = __floats2bfloat162_rn(v.x, v.y);
            __nv_bfloat162 p1 = __floats2bfloat162_rn(v.z, v.w);
            uint2 pk;
            pk.x = *(unsigned*)&p0;
            pk.y = *(unsigned*)&p1;
            *((uint2*)(x_s + row * XS_STRIDE + lane * 4)) = pk;
        }
        __syncthreads();
        #pragma unroll
        for (int kk = 0; kk < KC / 16; kk++) {
            unsigned a0 = *(const unsigned*)(x_s + (mrow + g) * XS_STRIDE + kk * 16 + t4 * 2);
            unsigned a1 = *(const unsigned*)(x_s + (mrow + g + 8) * XS_STRIDE + kk * 16 + t4 * 2);
            unsigned a2 = *(const unsigned*)(x_s + (mrow + g) * XS_STRIDE + kk * 16 + 8 + t4 * 2);
            unsigned a3 = *(const unsigned*)(x_s + (mrow + g + 8) * XS_STRIDE + kk * 16 + 8 + t4 * 2);
            int kglob = kc * KC + kk * 16;
            #pragma unroll
            for (int j = 0; j < 6; j++) {
                unsigned b0 = *(const unsigned*)(gw_s + (j * 8 + g) * GW_STRIDE + kglob + t4 * 2);
                unsigned b1 = *(const unsigned*)(gw_s + (j * 8 + g) * GW_STRIDE + kglob + 8 + t4 * 2);
                mma_bf16(acc[j], a0, a1, a2, a3, b0, b1);
            }
        }
        __syncthreads();
    }

    if (tid < MTILE) {
        float mu  = sum_s[tid] * (1.0f / DDIM);
        float var = sumsq_s[tid] * (1.0f / DDIM) - mu * mu;
        sum_s[tid]   = mu;
        sumsq_s[tid] = rsqrtf(var + 1e-5f);
    }
    __syncthreads();

    // epilogue: y = gelu(rinv*(acc - mu*sumgw) + cb), scatter per mma frag layout
    {
        int r0 = mrow + g, r1 = r0 + 8;
        float mu0 = sum_s[r0], ri0 = sumsq_s[r0];
        float mu1 = sum_s[r1], ri1 = sumsq_s[r1];
        #pragma unroll
        for (int j = 0; j < 6; j++) {
            int c0 = j * 8 + t4 * 2, c1 = c0 + 1;
            y_s[r0 * YS_STRIDE + c0] = gelu_exact(ri0 * (acc[j][0] - mu0 * sumgw_s[c0]) + cb_s[c0]);
            y_s[r0 * YS_STRIDE + c1] = gelu_exact(ri0 * (acc[j][1] - mu0 * sumgw_s[c1]) + cb_s[c1]);
            y_s[r1 * YS_STRIDE + c0] = gelu_exact(ri1 * (acc[j][2] - mu1 * sumgw_s[c0]) + cb_s[c0]);
            y_s[r1 * YS_STRIDE + c1] = gelu_exact(ri1 * (acc[j][3] - mu1 * sumgw_s[c1]) + cb_s[c1]);
        }
    }
    __syncthreads();

    // middle: h2 = gelu(A48 @ y + c48), 2 threads per token
    {
        int t = tid >> 1;
        int rbase = (tid & 1) * 24;
        const float* yrow = y_s + t * YS_STRIDE;
        float h2v[24];
        #pragma unroll
        for (int r = 0; r < 24; r++) h2v[r] = c48_s[rbase + r];
        for (int kp = 0; kp < RDIM; kp++) {
            float yv = yrow[kp];
            const float* arow = A48T_s + kp * RDIM + rbase;
            #pragma unroll
            for (int r = 0; r < 24; r++) h2v[r] += yv * arow[r];
        }
        __nv_bfloat16* op = g_h2 + (size_t)(tok0 + t) * RDIM + rbase;
        #pragma unroll
        for (int r = 0; r < 24; r += 2) {
            __nv_bfloat162 p = __floats2bfloat162_rn(gelu_exact(h2v[r]), gelu_exact(h2v[r + 1]));
            *((__nv_bfloat162*)(op + r)) = p;
        }
    }
}

// ============================================================================
// k2: out = x + scale * (h2 @ w_up^T). K=48 (3 mma k-steps), w_up resident in
// smem, A fragments loaded once per tile, residual fused in the epilogue.
// ============================================================================
__global__ __launch_bounds__(256) void k2_kernel(const float* __restrict__ x,
                                                 const float* __restrict__ scale_p,
                                                 float* __restrict__ out) {
    extern __shared__ char smem[];
    __nv_bfloat16* wu_s = (__nv_bfloat16*)smem;                            // 114688 B
    __nv_bfloat16* h2_s = (__nv_bfloat16*)(smem + DDIM * WU_STRIDE * 2);   // 14336 B

    int tid = threadIdx.x, lane = tid & 31, warp = tid >> 5;
    int g = lane >> 2, t4 = lane & 3;
    int tok0 = blockIdx.x * MTILE;

    for (int i = tid; i < DDIM * 6; i += 256) {
        int d = i / 6, c8 = i % 6;
        *((uint4*)(wu_s + d * WU_STRIDE + c8 * 8)) = ((const uint4*)g_wu)[i];
    }
    for (int i = tid; i < MTILE * 6; i += 256) {
        int t = i / 6, c8 = i % 6;
        *((uint4*)(h2_s + t * H2_STRIDE + c8 * 8)) =
            ((const uint4*)(g_h2 + (size_t)tok0 * RDIM))[i];
    }
    __syncthreads();

    float scale = *scale_p;
    int mrow = warp * 16;
    unsigned afr[3][4];
    #pragma unroll
    for (int kk = 0; kk < 3; kk++) {
        afr[kk][0] = *(const unsigned*)(h2_s + (mrow + g) * H2_STRIDE + kk * 16 + t4 * 2);
        afr[kk][1] = *(const unsigned*)(h2_s + (mrow + g + 8) * H2_STRIDE + kk * 16 + t4 * 2);
        afr[kk][2] = *(const unsigned*)(h2_s + (mrow + g) * H2_STRIDE + kk * 16 + 8 + t4 * 2);
        afr[kk][3] = *(const unsigned*)(h2_s + (mrow + g + 8) * H2_STRIDE + kk * 16 + 8 + t4 * 2);
    }

    for (int nb = 0; nb < DDIM / 64; nb++) {
        float acc[8][4];
        #pragma unroll
        for (int j = 0; j < 8; j++)
            #pragma unroll
            for (int q = 0; q < 4; q++) acc[j][q] = 0.f;

        #pragma unroll
        for (int kk = 0; kk < 3; kk++) {
            #pragma unroll
            for (int j = 0; j < 8; j++) {
                int n = nb * 64 + j * 8 + g;
                unsigned b0 = *(const unsigned*)(wu_s + n * WU_STRIDE + kk * 16 + t4 * 2);
                unsigned b1 = *(const unsigned*)(wu_s + n * WU_STRIDE + kk * 16 + 8 + t4 * 2);
                mma_bf16(acc[j], afr[kk][0], afr[kk][1], afr[kk][2], afr[kk][3], b0, b1);
            }
        }
        size_t row0 = (size_t)(tok0 + mrow + g) * DDIM;
        size_t row1 = row0 + 8 * (size_t)DDIM;
        #pragma unroll
        for (int j = 0; j < 8; j++) {
            int c = nb * 64 + j * 8 + t4 * 2;
            float2 xv0 = *(const float2*)(x + row0 + c);
            float2 xv1 = *(const float2*)(x + row1 + c);
            float2 o0 = make_float2(xv0.x + scale * acc[j][0], xv0.y + scale * acc[j][1]);
            float2 o1 = make_float2(xv1.x + scale * acc[j][2], xv1.y + scale * acc[j][3]);
            *((float2*)(out + row0 + c)) = o0;
            *((float2*)(out + row1 + c)) = o1;
        }
    }
}

extern "C" void kernel_launch(void* const* d_in, const int* in_sizes, int n_in,
                              void* d_out, int out_size) {
    const float* x         = (const float*)d_in[0];
    const float* gamma     = (const float*)d_in[1];
    const float* beta      = (const float*)d_in[2];
    const float* w_down    = (const float*)d_in[3];
    const float* w_to_mv   = (const float*)d_in[4];
    const float* w_equi    = (const float*)d_in[5];
    const float* b_equi    = (const float*)d_in[6];
    const float* w_from_mv = (const float*)d_in[7];
    const float* w_up      = (const float*)d_in[8];
    const float* scale     = (const float*)d_in[9];
    float* out = (float*)d_out;

    int smem1 = RDIM * GW_STRIDE * 2 + MTILE * XS_STRIDE * 2 + MTILE * YS_STRIDE * 4
              + MTILE * 4 * 2 + RDIM * 4 * 3 + RDIM * RDIM * 4;   // 171328 B
    int smem2 = DDIM * WU_STRIDE * 2 + MTILE * H2_STRIDE * 2;      // 129024 B
    cudaFuncSetAttribute(k1_kernel, cudaFuncAttributeMaxDynamicSharedMemorySize, smem1);
    cudaFuncSetAttribute(k2_kernel, cudaFuncAttributeMaxDynamicSharedMemorySize, smem2);

    prep_kernel<<<64, 256>>>(gamma, beta, w_down, w_to_mv, w_equi, b_equi, w_from_mv, w_up);
    k1_kernel<<<NCTAS, 256, smem1>>>(x);
    k2_kernel<<<NCTAS, 256, smem2>>>(x, scale, out);
}

// round 3
// speedup vs baseline: 1.7519x; 1.7519x over previous
#include <cuda_runtime.h>
#include <cuda_bf16.h>

#define TOKENS 32768
#define DDIM 1024
#define RDIM 48
#define MTILE 128
#define NCTAS (TOKENS / MTILE)   // 256
#define KC 128
#define XS_STRIDE 136            // bf16; 272B rows -> conflict-free frag LDS
#define GW_STRIDE 1032           // bf16; 2064B rows
#define YS_STRIDE 52
#define WU_STRIDE 56             // bf16; 112B rows
#define H2_STRIDE 56

// ---- shared memory layout (bytes). Regions overlaid by phase. ----
#define OFF_R0    0                               // gw_s (A) / wu_s (C)
#define SZ_R0     (DDIM * WU_STRIDE * 2)          // 114688 (>= gw 99072)
#define OFF_XS    (OFF_R0 + SZ_R0)                // x_s double buffer / h2_s
#define SZ_XS     (2 * MTILE * XS_STRIDE * 2)     // 69632
#define OFF_YS    (OFF_XS + SZ_XS)                // 26624
#define OFF_SUM   (OFF_YS + MTILE * YS_STRIDE * 4)
#define OFF_SUMSQ (OFF_SUM + MTILE * 4)
#define OFF_SGW   (OFF_SUMSQ + MTILE * 4)
#define OFF_CB    (OFF_SGW + RDIM * 4)
#define OFF_C48   (OFF_CB + RDIM * 4)
#define OFF_A48   (OFF_C48 + RDIM * 4)
#define SMEM_TOTAL (OFF_A48 + RDIM * RDIM * 4)    // 221760 B

__device__ __forceinline__ float gelu_exact(float v) {
    return 0.5f * v * (1.0f + erff(v * 0.70710678118654752440f));
}

__device__ __forceinline__ void mma_bf16(float* c, unsigned a0, unsigned a1, unsigned a2,
                                         unsigned a3, unsigned b0, unsigned b1) {
    asm volatile(
        "mma.sync.aligned.m16n8k16.row.col.f32.bf16.bf16.f32 "
        "{%0,%1,%2,%3}, {%4,%5,%6,%7}, {%8,%9}, {%0,%1,%2,%3};\n"
        : "+f"(c[0]), "+f"(c[1]), "+f"(c[2]), "+f"(c[3])
        : "r"(a0), "r"(a1), "r"(a2), "r"(a3), "r"(b0), "r"(b1));
}

__device__ __forceinline__ uint2 pack_bf16x4(float a, float b, float c, float d) {
    __nv_bfloat162 p0 = __floats2bfloat162_rn(a, b);
    __nv_bfloat162 p1 = __floats2bfloat162_rn(c, d);
    uint2 pk;
    pk.x = *(unsigned*)&p0;
    pk.y = *(unsigned*)&p1;
    return pk;
}

// ============================================================================
// Fully fused: LN-fold + down-GEMM + gelu + collapsed 48x48 middle + gelu +
// up-GEMM + residual. One CTA per 128-token tile. No prep kernel, no global
// scratch — all weight preprocessing done per-CTA into smem from L2-hot data.
// ============================================================================
__global__ void __launch_bounds__(256) fused_kernel(
    const float* __restrict__ x, const float* __restrict__ gamma,
    const float* __restrict__ beta, const float* __restrict__ w_down,
    const float* __restrict__ w_to_mv, const float* __restrict__ w_equi,
    const float* __restrict__ b_equi, const float* __restrict__ w_from_mv,
    const float* __restrict__ w_up, const float* __restrict__ scale_p,
    float* __restrict__ out)
{
    extern __shared__ char smem[];
    __nv_bfloat16* gw_s  = (__nv_bfloat16*)(smem + OFF_R0);
    __nv_bfloat16* wu_s  = (__nv_bfloat16*)(smem + OFF_R0);
    __nv_bfloat16* x_s   = (__nv_bfloat16*)(smem + OFF_XS);
    __nv_bfloat16* h2_s  = (__nv_bfloat16*)(smem + OFF_XS);
    float* y_s     = (float*)(smem + OFF_YS);
    float* sum_s   = (float*)(smem + OFF_SUM);
    float* sumsq_s = (float*)(smem + OFF_SUMSQ);
    float* sumgw_s = (float*)(smem + OFF_SGW);
    float* cb_s    = (float*)(smem + OFF_CB);
    float* c48_s   = (float*)(smem + OFF_C48);
    float* A48T_s  = (float*)(smem + OFF_A48);

    const int tid = threadIdx.x, lane = tid & 31, warp = tid >> 5;
    const int g = lane >> 2, t4 = lane & 3;
    const int tok0 = blockIdx.x * MTILE;
    const int mrow = warp * 16;

    // ---- stage gw = gamma (*) w_down as bf16 (reads are L2-broadcast hot) ----
    {
        const float4* wd4 = (const float4*)w_down;
        const float4* g4  = (const float4*)gamma;
        for (int i = tid; i < RDIM * DDIM / 4; i += 256) {
            int r = i >> 8, c = i & 255;
            float4 w = wd4[i];
            float4 gv = g4[c];
            *(uint2*)(gw_s + r * GW_STRIDE + c * 4) =
                pack_bf16x4(w.x * gv.x, w.y * gv.y, w.z * gv.z, w.w * gv.w);
        }
    }

    // ---- phase A: stream x once; stats in registers; down mma, double-buffered ----
    float4 st[16];
    {
        const float* p = x + (size_t)tok0 * DDIM;
        #pragma unroll
        for (int i = 0; i < 16; i++)
            st[i] = *(const float4*)(p + (size_t)(i * 8 + warp) * DDIM + lane * 4);
    }
    float ps[16], pss[16];
    #pragma unroll
    for (int i = 0; i < 16; i++) { ps[i] = 0.f; pss[i] = 0.f; }

    float acc[6][4];
    #pragma unroll
    for (int j = 0; j < 6; j++)
        #pragma unroll
        for (int q = 0; q < 4; q++) acc[j][q] = 0.f;

    #pragma unroll 2
    for (int kc = 0; kc < DDIM / KC; kc++) {
        __nv_bfloat16* xb = x_s + (kc & 1) * (MTILE * XS_STRIDE);
        #pragma unroll
        for (int i = 0; i < 16; i++) {
            float4 v = st[i];
            ps[i]  += (v.x + v.y) + (v.z + v.w);
            pss[i] += (v.x * v.x + v.y * v.y) + (v.z * v.z + v.w * v.w);
            *(uint2*)(xb + (i * 8 + warp) * XS_STRIDE + lane * 4) =
                pack_bf16x4(v.x, v.y, v.z, v.w);
        }
        __syncthreads();   // single barrier/iter is safe with 2 buffers
        if (kc < 7) {
            const float* p = x + (size_t)tok0 * DDIM + (kc + 1) * KC;
            #pragma unroll
            for (int i = 0; i < 16; i++)
                st[i] = *(const float4*)(p + (size_t)(i * 8 + warp) * DDIM + lane * 4);
        }
        #pragma unroll
        for (int kk = 0; kk < KC / 16; kk++) {
            unsigned a0 = *(const unsigned*)(xb + (mrow + g) * XS_STRIDE + kk * 16 + t4 * 2);
            unsigned a1 = *(const unsigned*)(xb + (mrow + g + 8) * XS_STRIDE + kk * 16 + t4 * 2);
            unsigned a2 = *(const unsigned*)(xb + (mrow + g) * XS_STRIDE + kk * 16 + 8 + t4 * 2);
            unsigned a3 = *(const unsigned*)(xb + (mrow + g + 8) * XS_STRIDE + kk * 16 + 8 + t4 * 2);
            int kglob = kc * KC + kk * 16;
            #pragma unroll
            for (int j = 0; j < 6; j++) {
                unsigned b0 = *(const unsigned*)(gw_s + (j * 8 + g) * GW_STRIDE + kglob + t4 * 2);
                unsigned b1 = *(const unsigned*)(gw_s + (j * 8 + g) * GW_STRIDE + kglob + 8 + t4 * 2);
                mma_bf16(acc[j], a0, a1, a2, a3, b0, b1);
            }
        }
    }

    // ---- stats: one shfl-tree per row, ONCE (not per load) ----
    #pragma unroll
    for (int i = 0; i < 16; i++) {
        float s = ps[i], q = pss[i];
        #pragma unroll
        for (int off = 16; off; off >>= 1) {
            s += __shfl_xor_sync(0xffffffffu, s, off);
            q += __shfl_xor_sync(0xffffffffu, q, off);
        }
        if (lane == 0) { sum_s[i * 8 + warp] = s; sumsq_s[i * 8 + warp] = q; }
    }

    // ---- per-CTA weight prep: sumgw (from bf16 gw, consistent w/ mma), cb, A48T, c48 ----
    #pragma unroll 1
    for (int rr = 0; rr < 6; rr++) {
        int r = warp + rr * 8;
        float sg = 0.f, scb = 0.f;
        #pragma unroll
        for (int it = 0; it < 8; it++) {
            int d = it * 128 + lane * 4;
            uint2 pk = *(const uint2*)(gw_s + r * GW_STRIDE + d);
            __nv_bfloat162 b0 = *(__nv_bfloat162*)&pk.x;
            __nv_bfloat162 b1 = *(__nv_bfloat162*)&pk.y;
            sg += __bfloat162float(b0.x) + __bfloat162float(b0.y)
                + __bfloat162float(b1.x) + __bfloat162float(b1.y);
            float4 wv = *(const float4*)(w_down + (size_t)r * DDIM + d);
            float4 bv = *(const float4*)(beta + d);
            scb += wv.x * bv.x + wv.y * bv.y + wv.z * bv.z + wv.w * bv.w;
        }
        #pragma unroll
        for (int off = 16; off; off >>= 1) {
            sg  += __shfl_xor_sync(0xffffffffu, sg, off);
            scb += __shfl_xor_sync(0xffffffffu, scb, off);
        }
        if (lane == 0) { sumgw_s[r] = sg; cb_s[r] = scb; }
    }
    for (int i = tid; i < RDIM; i += 256)
        c48_s[i] = __ldg(w_from_mv + i * 16) * __ldg(b_equi);
    for (int i = tid; i < RDIM * RDIM; i += 256) {
        int rp = i / RDIM, r = i - rp * RDIM;
        float a = 0.f;
        #pragma unroll
        for (int m = 0; m < 16; m++) {
            int gidx = (m == 0) ? 0 : (m < 5) ? 1 : (m < 11) ? 2 : (m < 15) ? 3 : 4;
            a += __ldg(w_from_mv + r * 16 + m) * __ldg(w_equi + gidx)
               * __ldg(w_to_mv + m * RDIM + rp);
        }
        A48T_s[i] = a;   // A48T[rp][r]
    }
    __syncthreads();
    if (tid < MTILE) {
        float mu  = sum_s[tid] * (1.0f / DDIM);
        float var = sumsq_s[tid] * (1.0f / DDIM) - mu * mu;
        sum_s[tid]   = mu;
        sumsq_s[tid] = rsqrtf(var + 1e-5f);
    }
    __syncthreads();

    // ---- epilogue: y = gelu(rinv*(acc - mu*sumgw) + cb) ----
    {
        int r0 = mrow + g, r1 = r0 + 8;
        float mu0 = sum_s[r0], ri0 = sumsq_s[r0];
        float mu1 = sum_s[r1], ri1 = sumsq_s[r1];
        #pragma unroll
        for (int j = 0; j < 6; j++) {
            int c0 = j * 8 + t4 * 2, c1 = c0 + 1;
            y_s[r0 * YS_STRIDE + c0] = gelu_exact(ri0 * (acc[j][0] - mu0 * sumgw_s[c0]) + cb_s[c0]);
            y_s[r0 * YS_STRIDE + c1] = gelu_exact(ri0 * (acc[j][1] - mu0 * sumgw_s[c1]) + cb_s[c1]);
            y_s[r1 * YS_STRIDE + c0] = gelu_exact(ri1 * (acc[j][2] - mu1 * sumgw_s[c0]) + cb_s[c0]);
            y_s[r1 * YS_STRIDE + c1] = gelu_exact(ri1 * (acc[j][3] - mu1 * sumgw_s[c1]) + cb_s[c1]);
        }
    }

    // ---- stage w_up as bf16 into region0 (gw_s dead after the loops above) ----
    {
        const float4* wu4 = (const float4*)w_up;
        for (int i = tid; i < DDIM * RDIM / 4; i += 256) {
            int d = i / 12, q = i - d * 12;
            float4 v = wu4[i];
            *(uint2*)(wu_s + d * WU_STRIDE + q * 4) = pack_bf16x4(v.x, v.y, v.z, v.w);
        }
    }
    __syncthreads();

    // ---- middle: h2 = gelu(A48 @ y + c48) -> bf16 smem (overlays x_s) ----
    {
        int t = tid >> 1;
        int rbase = (tid & 1) * 24;
        const float* yrow = y_s + t * YS_STRIDE;
        float h2v[24];
        #pragma unroll
        for (int r = 0; r < 24; r++) h2v[r] = c48_s[rbase + r];
        #pragma unroll 4
        for (int kp = 0; kp < RDIM; kp++) {
            float yv = yrow[kp];
            const float* arow = A48T_s + kp * RDIM + rbase;
            #pragma unroll
            for (int r = 0; r < 24; r++) h2v[r] += yv * arow[r];
        }
        __nv_bfloat16* op = h2_s + t * H2_STRIDE + rbase;
        #pragma unroll
        for (int r = 0; r < 24; r += 2) {
            __nv_bfloat162 p = __floats2bfloat162_rn(gelu_exact(h2v[r]), gelu_exact(h2v[r + 1]));
            *(__nv_bfloat162*)(op + r) = p;
        }
    }
    __syncthreads();

    // ---- phase C: out = x + scale * (h2 @ w_up^T) ----
    float scale = __ldg(scale_p);
    unsigned afr[3][4];
    #pragma unroll
    for (int kk = 0; kk < 3; kk++) {
        afr[kk][0] = *(const unsigned*)(h2_s + (mrow + g) * H2_STRIDE + kk * 16 + t4 * 2);
        afr[kk][1] = *(const unsigned*)(h2_s + (mrow + g + 8) * H2_STRIDE + kk * 16 + t4 * 2);
        afr[kk][2] = *(const unsigned*)(h2_s + (mrow + g) * H2_STRIDE + kk * 16 + 8 + t4 * 2);
        afr[kk][3] = *(const unsigned*)(h2_s + (mrow + g + 8) * H2_STRIDE + kk * 16 + 8 + t4 * 2);
    }

    #pragma unroll 1
    for (int nb = 0; nb < DDIM / 64; nb++) {
        float uacc[8][4];
        #pragma unroll
        for (int j = 0; j < 8; j++)
            #pragma unroll
            for (int q = 0; q < 4; q++) uacc[j][q] = 0.f;

        #pragma unroll
        for (int kk = 0; kk < 3; kk++) {
            #pragma unroll
            for (int j = 0; j < 8; j++) {
                int n = nb * 64 + j * 8 + g;
                unsigned b0 = *(const unsigned*)(wu_s + n * WU_STRIDE + kk * 16 + t4 * 2);
                unsigned b1 = *(const unsigned*)(wu_s + n * WU_STRIDE + kk * 16 + 8 + t4 * 2);
                mma_bf16(uacc[j], afr[kk][0], afr[kk][1], afr[kk][2], afr[kk][3], b0, b1);
            }
        }
        size_t row0 = (size_t)(tok0 + mrow + g) * DDIM;
        size_t row1 = row0 + 8 * (size_t)DDIM;
        #pragma unroll
        for (int j = 0; j < 8; j++) {
            int c = nb * 64 + j * 8 + t4 * 2;
            float2 xv0 = *(const float2*)(x + row0 + c);
            float2 xv1 = *(const float2*)(x + row1 + c);
            float2 o0 = make_float2(xv0.x + scale * uacc[j][0], xv0.y + scale * uacc[j][1]);
            float2 o1 = make_float2(xv1.x + scale * uacc[j][2], xv1.y + scale * uacc[j][3]);
            __stcs((float2*)(out + row0 + c), o0);   // streaming: don't pollute L2
            __stcs((float2*)(out + row1 + c), o1);
        }
    }
}

extern "C" void kernel_launch(void* const* d_in, const int* in_sizes, int n_in,
                              void* d_out, int out_size) {
    const float* x         = (const float*)d_in[0];
    const float* gamma     = (const float*)d_in[1];
    const float* beta      = (const float*)d_in[2];
    const float* w_down    = (const float*)d_in[3];
    const float* w_to_mv   = (const float*)d_in[4];
    const float* w_equi    = (const float*)d_in[5];
    const float* b_equi    = (const float*)d_in[6];
    const float* w_from_mv = (const float*)d_in[7];
    const float* w_up      = (const float*)d_in[8];
    const float* scale     = (const float*)d_in[9];
    float* out = (float*)d_out;

    cudaFuncSetAttribute(fused_kernel, cudaFuncAttributeMaxDynamicSharedMemorySize, SMEM_TOTAL);
    fused_kernel<<<NCTAS, 256, SMEM_TOTAL>>>(x, gamma, beta, w_down, w_to_mv, w_equi,
                                             b_equi, w_from_mv, w_up, scale, out);
}

// round 4
// speedup vs baseline: 2.0862x; 1.1909x over previous
#include <cuda_runtime.h>
#include <cuda_bf16.h>

#define TOKENS 32768
#define DDIM 1024
#define RDIM 48
#define MTILE 256
#define THREADS 512
#define NCTAS (TOKENS / MTILE)   // 128 -> single wave on 148 SMs
#define KC 64
#define NCHUNK (DDIM / KC)       // 16
#define XS_STRIDE 72             // bf16; 144B rows -> conflict-free frag LDS
#define GW_STRIDE 1032           // bf16; 2064B rows
#define YS_STRIDE 52             // bf16 now
#define WU_STRIDE 56             // bf16; 112B rows
#define H2_STRIDE 56

// ---- shared memory layout (bytes). Regions overlaid by phase. ----
#define OFF_R0    0                               // gw_s (A) / wu_s (C)
#define SZ_R0     (DDIM * WU_STRIDE * 2)          // 114688 (>= gw 99072)
#define OFF_XS    (OFF_R0 + SZ_R0)                // x_s double buffer / h2_s
#define SZ_XS     (2 * MTILE * XS_STRIDE * 2)     // 73728 (>= h2 28672)
#define OFF_YS    (OFF_XS + SZ_XS)                // y bf16: 26624
#define OFF_SUM   (OFF_YS + MTILE * YS_STRIDE * 2)
#define OFF_SUMSQ (OFF_SUM + MTILE * 4)
#define OFF_SGW   (OFF_SUMSQ + MTILE * 4)
#define OFF_CB    (OFF_SGW + RDIM * 4)
#define OFF_C48   (OFF_CB + RDIM * 4)
#define OFF_A48   (OFF_C48 + RDIM * 4)
#define SMEM_TOTAL (OFF_A48 + RDIM * RDIM * 4)    // 226880 B <= 232448

__device__ __forceinline__ float gelu_exact(float v) {
    return 0.5f * v * (1.0f + erff(v * 0.70710678118654752440f));
}

__device__ __forceinline__ void mma_bf16(float* c, unsigned a0, unsigned a1, unsigned a2,
                                         unsigned a3, unsigned b0, unsigned b1) {
    asm volatile(
        "mma.sync.aligned.m16n8k16.row.col.f32.bf16.bf16.f32 "
        "{%0,%1,%2,%3}, {%4,%5,%6,%7}, {%8,%9}, {%0,%1,%2,%3};\n"
        : "+f"(c[0]), "+f"(c[1]), "+f"(c[2]), "+f"(c[3])
        : "r"(a0), "r"(a1), "r"(a2), "r"(a3), "r"(b0), "r"(b1));
}

__device__ __forceinline__ uint2 pack_bf16x4(float a, float b, float c, float d) {
    __nv_bfloat162 p0 = __floats2bfloat162_rn(a, b);
    __nv_bfloat162 p1 = __floats2bfloat162_rn(c, d);
    uint2 pk;
    pk.x = *(unsigned*)&p0;
    pk.y = *(unsigned*)&p1;
    return pk;
}

// ============================================================================
// Fully fused, 512 threads / 256-token tile, 128 CTAs = one full wave.
// ============================================================================
__global__ void __launch_bounds__(THREADS, 1) fused_kernel(
    const float* __restrict__ x, const float* __restrict__ gamma,
    const float* __restrict__ beta, const float* __restrict__ w_down,
    const float* __restrict__ w_to_mv, const float* __restrict__ w_equi,
    const float* __restrict__ b_equi, const float* __restrict__ w_from_mv,
    const float* __restrict__ w_up, const float* __restrict__ scale_p,
    float* __restrict__ out)
{
    extern __shared__ char smem[];
    __nv_bfloat16* gw_s = (__nv_bfloat16*)(smem + OFF_R0);
    __nv_bfloat16* wu_s = (__nv_bfloat16*)(smem + OFF_R0);
    __nv_bfloat16* x_s  = (__nv_bfloat16*)(smem + OFF_XS);
    __nv_bfloat16* h2_s = (__nv_bfloat16*)(smem + OFF_XS);
    __nv_bfloat16* y_s  = (__nv_bfloat16*)(smem + OFF_YS);
    float* sum_s   = (float*)(smem + OFF_SUM);
    float* sumsq_s = (float*)(smem + OFF_SUMSQ);
    float* sumgw_s = (float*)(smem + OFF_SGW);
    float* cb_s    = (float*)(smem + OFF_CB);
    float* c48_s   = (float*)(smem + OFF_C48);
    float* A48T_s  = (float*)(smem + OFF_A48);

    const int tid = threadIdx.x, lane = tid & 31, warp = tid >> 5;
    const int g = lane >> 2, t4 = lane & 3;
    const int half = lane >> 4, c16 = lane & 15;       // phase-A load mapping
    const int tok0 = blockIdx.x * MTILE;
    const int mrow = warp * 16;

    // ---- stage gw = gamma (*) w_down as bf16 ----
    {
        const float4* wd4 = (const float4*)w_down;
        const float4* g4  = (const float4*)gamma;
        for (int i = tid; i < RDIM * DDIM / 4; i += THREADS) {
            int r = i >> 8, c = i & 255;
            float4 w = wd4[i];
            float4 gv = g4[c];
            *(uint2*)(gw_s + r * GW_STRIDE + c * 4) =
                pack_bf16x4(w.x * gv.x, w.y * gv.y, w.z * gv.z, w.w * gv.w);
        }
    }

    // ---- phase A: warp owns rows [mrow, mrow+16); step i loads rows mrow+i*2+half ----
    float4 st[8];
    {
        const float* p = x + (size_t)tok0 * DDIM + c16 * 4;
        #pragma unroll
        for (int i = 0; i < 8; i++)
            st[i] = *(const float4*)(p + (size_t)(mrow + i * 2 + half) * DDIM);
    }
    float ps[8], pss[8];
    #pragma unroll
    for (int i = 0; i < 8; i++) { ps[i] = 0.f; pss[i] = 0.f; }

    float acc[6][4];
    #pragma unroll
    for (int j = 0; j < 6; j++)
        #pragma unroll
        for (int q = 0; q < 4; q++) acc[j][q] = 0.f;

    #pragma unroll 2
    for (int kc = 0; kc < NCHUNK; kc++) {
        __nv_bfloat16* xb = x_s + (kc & 1) * (MTILE * XS_STRIDE);
        #pragma unroll
        for (int i = 0; i < 8; i++) {
            float4 v = st[i];
            ps[i]  += (v.x + v.y) + (v.z + v.w);
            pss[i] += (v.x * v.x + v.y * v.y) + (v.z * v.z + v.w * v.w);
            *(uint2*)(xb + (mrow + i * 2 + half) * XS_STRIDE + c16 * 4) =
                pack_bf16x4(v.x, v.y, v.z, v.w);
        }
        __syncthreads();   // single barrier/iter safe with 2 buffers
        if (kc < NCHUNK - 1) {
            const float* p = x + (size_t)tok0 * DDIM + (kc + 1) * KC + c16 * 4;
            #pragma unroll
            for (int i = 0; i < 8; i++)
                st[i] = *(const float4*)(p + (size_t)(mrow + i * 2 + half) * DDIM);
        }
        #pragma unroll
        for (int kk = 0; kk < KC / 16; kk++) {
            unsigned a0 = *(const unsigned*)(xb + (mrow + g) * XS_STRIDE + kk * 16 + t4 * 2);
            unsigned a1 = *(const unsigned*)(xb + (mrow + g + 8) * XS_STRIDE + kk * 16 + t4 * 2);
            unsigned a2 = *(const unsigned*)(xb + (mrow + g) * XS_STRIDE + kk * 16 + 8 + t4 * 2);
            unsigned a3 = *(const unsigned*)(xb + (mrow + g + 8) * XS_STRIDE + kk * 16 + 8 + t4 * 2);
            int kglob = kc * KC + kk * 16;
            #pragma unroll
            for (int j = 0; j < 6; j++) {
                unsigned b0 = *(const unsigned*)(gw_s + (j * 8 + g) * GW_STRIDE + kglob + t4 * 2);
                unsigned b1 = *(const unsigned*)(gw_s + (j * 8 + g) * GW_STRIDE + kglob + 8 + t4 * 2);
                mma_bf16(acc[j], a0, a1, a2, a3, b0, b1);
            }
        }
    }

    // ---- stats: one reduction over the 16 lanes sharing each row ----
    #pragma unroll
    for (int i = 0; i < 8; i++) {
        float s = ps[i], q = pss[i];
        #pragma unroll
        for (int off = 8; off; off >>= 1) {
            s += __shfl_xor_sync(0xffffffffu, s, off);
            q += __shfl_xor_sync(0xffffffffu, q, off);
        }
        if (c16 == 0) {
            sum_s[mrow + i * 2 + half] = s;
            sumsq_s[mrow + i * 2 + half] = q;
        }
    }

    // ---- per-CTA weight prep: sumgw (from bf16 gw), cb, c48, A48T ----
    #pragma unroll 1
    for (int rr = 0; rr < 3; rr++) {
        int r = warp + rr * 16;
        float sg = 0.f, scb = 0.f;
        #pragma unroll
        for (int it = 0; it < 8; it++) {
            int d = it * 128 + lane * 4;
            uint2 pk = *(const uint2*)(gw_s + r * GW_STRIDE + d);
            __nv_bfloat162 b0 = *(__nv_bfloat162*)&pk.x;
            __nv_bfloat162 b1 = *(__nv_bfloat162*)&pk.y;
            sg += __bfloat162float(b0.x) + __bfloat162float(b0.y)
                + __bfloat162float(b1.x) + __bfloat162float(b1.y);
            float4 wv = *(const float4*)(w_down + (size_t)r * DDIM + d);
            float4 bv = *(const float4*)(beta + d);
            scb += wv.x * bv.x + wv.y * bv.y + wv.z * bv.z + wv.w * bv.w;
        }
        #pragma unroll
        for (int off = 16; off; off >>= 1) {
            sg  += __shfl_xor_sync(0xffffffffu, sg, off);
            scb += __shfl_xor_sync(0xffffffffu, scb, off);
        }
        if (lane == 0) { sumgw_s[r] = sg; cb_s[r] = scb; }
    }
    for (int i = tid; i < RDIM; i += THREADS)
        c48_s[i] = __ldg(w_from_mv + i * 16) * __ldg(b_equi);
    for (int i = tid; i < RDIM * RDIM; i += THREADS) {
        int rp = i / RDIM, r = i - rp * RDIM;
        float a = 0.f;
        #pragma unroll
        for (int m = 0; m < 16; m++) {
            int gidx = (m == 0) ? 0 : (m < 5) ? 1 : (m < 11) ? 2 : (m < 15) ? 3 : 4;
            a += __ldg(w_from_mv + r * 16 + m) * __ldg(w_equi + gidx)
               * __ldg(w_to_mv + m * RDIM + rp);
        }
        A48T_s[i] = a;   // A48T[rp][r]
    }
    __syncthreads();
    if (tid < MTILE) {
        float mu  = sum_s[tid] * (1.0f / DDIM);
        float var = sumsq_s[tid] * (1.0f / DDIM) - mu * mu;
        sum_s[tid]   = mu;
        sumsq_s[tid] = rsqrtf(var + 1e-5f);
    }
    __syncthreads();

    // ---- epilogue: y = gelu(rinv*(acc - mu*sumgw) + cb) -> bf16 ----
    {
        int r0 = mrow + g, r1 = r0 + 8;
        float mu0 = sum_s[r0], ri0 = sumsq_s[r0];
        float mu1 = sum_s[r1], ri1 = sumsq_s[r1];
        #pragma unroll
        for (int j = 0; j < 6; j++) {
            int c0 = j * 8 + t4 * 2, c1 = c0 + 1;
            float y00 = gelu_exact(ri0 * (acc[j][0] - mu0 * sumgw_s[c0]) + cb_s[c0]);
            float y01 = gelu_exact(ri0 * (acc[j][1] - mu0 * sumgw_s[c1]) + cb_s[c1]);
            float y10 = gelu_exact(ri1 * (acc[j][2] - mu1 * sumgw_s[c0]) + cb_s[c0]);
            float y11 = gelu_exact(ri1 * (acc[j][3] - mu1 * sumgw_s[c1]) + cb_s[c1]);
            *(__nv_bfloat162*)(y_s + r0 * YS_STRIDE + c0) = __floats2bfloat162_rn(y00, y01);
            *(__nv_bfloat162*)(y_s + r1 * YS_STRIDE + c0) = __floats2bfloat162_rn(y10, y11);
        }
    }

    // ---- stage w_up as bf16 into region0 (gw_s dead: two syncs since last read) ----
    {
        const float4* wu4 = (const float4*)w_up;
        for (int i = tid; i < DDIM * RDIM / 4; i += THREADS) {
            int d = i / 12, q = i - d * 12;
            float4 v = wu4[i];
            *(uint2*)(wu_s + d * WU_STRIDE + q * 4) = pack_bf16x4(v.x, v.y, v.z, v.w);
        }
    }
    __syncthreads();

    // ---- middle: h2 = gelu(A48 @ y + c48) -> bf16 (overlays x_s; x_s dead) ----
    {
        int t = tid >> 1;
        int rbase = (tid & 1) * 24;
        const __nv_bfloat16* yrow = y_s + t * YS_STRIDE;
        float h2v[24];
        #pragma unroll
        for (int r = 0; r < 24; r++) h2v[r] = c48_s[rbase + r];
        #pragma unroll 4
        for (int kp2 = 0; kp2 < RDIM / 2; kp2++) {
            __nv_bfloat162 yp = *(const __nv_bfloat162*)(yrow + kp2 * 2);
            float yv0 = __bfloat162float(yp.x), yv1 = __bfloat162float(yp.y);
            const float* a0 = A48T_s + (kp2 * 2) * RDIM + rbase;
            const float* a1 = a0 + RDIM;
            #pragma unroll
            for (int r = 0; r < 24; r++) h2v[r] += yv0 * a0[r] + yv1 * a1[r];
        }
        __nv_bfloat16* op = h2_s + t * H2_STRIDE + rbase;
        #pragma unroll
        for (int r = 0; r < 24; r += 2) {
            __nv_bfloat162 p = __floats2bfloat162_rn(gelu_exact(h2v[r]), gelu_exact(h2v[r + 1]));
            *(__nv_bfloat162*)(op + r) = p;
        }
    }
    __syncthreads();

    // ---- phase C: out = x + scale * (h2 @ w_up^T) ----
    float scale = __ldg(scale_p);
    unsigned afr[3][4];
    #pragma unroll
    for (int kk = 0; kk < 3; kk++) {
        afr[kk][0] = *(const unsigned*)(h2_s + (mrow + g) * H2_STRIDE + kk * 16 + t4 * 2);
        afr[kk][1] = *(const unsigned*)(h2_s + (mrow + g + 8) * H2_STRIDE + kk * 16 + t4 * 2);
        afr[kk][2] = *(const unsigned*)(h2_s + (mrow + g) * H2_STRIDE + kk * 16 + 8 + t4 * 2);
        afr[kk][3] = *(const unsigned*)(h2_s + (mrow + g + 8) * H2_STRIDE + kk * 16 + 8 + t4 * 2);
    }

    #pragma unroll 1
    for (int nb = 0; nb < DDIM / 64; nb++) {
        size_t row0 = (size_t)(tok0 + mrow + g) * DDIM;
        size_t row1 = row0 + 8 * (size_t)DDIM;

        // issue residual x loads FIRST so LDG latency overlaps the mma block
        float2 xv0[8], xv1[8];
        #pragma unroll
        for (int j = 0; j < 8; j++) {
            int c = nb * 64 + j * 8 + t4 * 2;
            xv0[j] = *(const float2*)(x + row0 + c);
            xv1[j] = *(const float2*)(x + row1 + c);
        }

        float uacc[8][4];
        #pragma unroll
        for (int j = 0; j < 8; j++)
            #pragma unroll
            for (int q = 0; q < 4; q++) uacc[j][q] = 0.f;

        #pragma unroll
        for (int kk = 0; kk < 3; kk++) {
            #pragma unroll
            for (int j = 0; j < 8; j++) {
                int n = nb * 64 + j * 8 + g;
                unsigned b0 = *(const unsigned*)(wu_s + n * WU_STRIDE + kk * 16 + t4 * 2);
                unsigned b1 = *(const unsigned*)(wu_s + n * WU_STRIDE + kk * 16 + 8 + t4 * 2);
                mma_bf16(uacc[j], afr[kk][0], afr[kk][1], afr[kk][2], afr[kk][3], b0, b1);
            }
        }
        #pragma unroll
        for (int j = 0; j < 8; j++) {
            int c = nb * 64 + j * 8 + t4 * 2;
            float2 o0 = make_float2(xv0[j].x + scale * uacc[j][0], xv0[j].y + scale * uacc[j][1]);
            float2 o1 = make_float2(xv1[j].x + scale * uacc[j][2], xv1[j].y + scale * uacc[j][3]);
            __stcs((float2*)(out + row0 + c), o0);
            __stcs((float2*)(out + row1 + c), o1);
        }
    }
}

extern "C" void kernel_launch(void* const* d_in, const int* in_sizes, int n_in,
                              void* d_out, int out_size) {
    const float* x         = (const float*)d_in[0];
    const float* gamma     = (const float*)d_in[1];
    const float* beta      = (const float*)d_in[2];
    const float* w_down    = (const float*)d_in[3];
    const float* w_to_mv   = (const float*)d_in[4];
    const float* w_equi    = (const float*)d_in[5];
    const float* b_equi    = (const float*)d_in[6];
    const float* w_from_mv = (const float*)d_in[7];
    const float* w_up      = (const float*)d_in[8];
    const float* scale     = (const float*)d_in[9];
    float* out = (float*)d_out;

    cudaFuncSetAttribute(fused_kernel, cudaFuncAttributeMaxDynamicSharedMemorySize, SMEM_TOTAL);
    fused_kernel<<<NCTAS, THREADS, SMEM_TOTAL>>>(x, gamma, beta, w_down, w_to_mv, w_equi,
                                                 b_equi, w_from_mv, w_up, scale, out);
}